// round 7
// baseline (speedup 1.0000x reference)
#include <cuda_runtime.h>
#include <cstdint>

// Grayscale erosion, 5x5 non-flat SE, 'same' padding with +inf.
// out[p,y,x] = min_{i,j in 0..4} img[p, y+i-2, x+j-2] - filt[i,j]
//
// Compute-bound design: 50 fp32 ops/pixel is the floor (25 FADD + 25 FMNMX).
// Register-block 4x4 outputs per thread; stage input tile in smem with
// vectorized fill (interior fast path) and vectorized LDS.128 patch reads.

#define WIDTH   1024
#define HEIGHT  1024
#define TILE_X  128      // output cols per block
#define TILE_Y  32       // output rows per block
#define RX      4        // output cols per thread
#define RY      4        // output rows per thread
#define BDX     32       // TILE_X / RX
#define BDY     8        // TILE_Y / RY
// smem tile covers gmem cols [x0-4, x0+131] (2 wasted cols each side for
// 16B-aligned vector loads) and rows [y0-2, y0+33].
#define SW      136
#define SH      36
#define SW4     (SW/4)   // 34 float4 per row
#define FINF    __int_as_float(0x7f800000)

__global__ __launch_bounds__(BDX * BDY)
void erosion5x5_kernel(const float* __restrict__ img,
                       const float* __restrict__ filt,
                       float* __restrict__ out)
{
    __shared__ __align__(16) float s_tile[SH][SW];
    __shared__ float s_nf[25];

    const int tx  = threadIdx.x;           // 0..31
    const int ty  = threadIdx.y;           // 0..7
    const int tid = ty * BDX + tx;         // 0..255

    const int x0 = blockIdx.x * TILE_X;
    const int y0 = blockIdx.y * TILE_Y;
    const float* __restrict__ p =
        img + (size_t)blockIdx.z * (size_t)(WIDTH * HEIGHT);

    // negated filter -> smem (so inner loop is FADD, min identity preserved)
    if (tid < 25) s_nf[tid] = -filt[tid];

    // ---- stage input tile into smem ----
    const bool interior = (x0 >= 4) && (x0 + SW - 4 <= WIDTH) &&
                          (y0 >= 2) && (y0 + SH - 2 <= HEIGHT);
    if (interior) {
        // 34*36 = 1224 float4 transfers, fully aligned, no bounds checks
        const float4* __restrict__ g =
            reinterpret_cast<const float4*>(p + (size_t)(y0 - 2) * WIDTH + (x0 - 4));
        float4* __restrict__ s = reinterpret_cast<float4*>(&s_tile[0][0]);
        #pragma unroll
        for (int q = tid; q < SH * SW4; q += BDX * BDY) {
            int r  = q / SW4;
            int c4 = q - r * SW4;
            s[q] = g[(size_t)r * (WIDTH / 4) + c4];
        }
    } else {
        // scalar fill with +inf padding
        for (int idx = tid; idx < SH * SW; idx += BDX * BDY) {
            int r  = idx / SW;
            int c  = idx - r * SW;
            int gr = y0 - 2 + r;
            int gc = x0 - 4 + c;
            float v = FINF;
            if (gr >= 0 && gr < HEIGHT && gc >= 0 && gc < WIDTH)
                v = p[(size_t)gr * WIDTH + gc];
            s_tile[r][c] = v;
        }
    }
    __syncthreads();

    // negated filter into registers (LDS broadcast, conflict-free)
    float nf[25];
    #pragma unroll
    for (int i = 0; i < 25; ++i) nf[i] = s_nf[i];

    // ---- compute 4x4 outputs per thread ----
    float acc[RY][RX];
    #pragma unroll
    for (int r = 0; r < RY; ++r)
        #pragma unroll
        for (int c = 0; c < RX; ++c)
            acc[r][c] = FINF;

    const int srow0 = ty * RY;      // smem row of patch row 0 (= output row 0 - 2, rebased)
    const int scol0 = tx * RX;      // smem col of patch col 0 (= output col 0 - 2, rebased w/ +2 skew)

    #pragma unroll
    for (int i = 0; i < RY + 4; ++i) {
        // load 12 contiguous floats (3x LDS.128), patch uses v[2..9]
        const float4* rowp =
            reinterpret_cast<const float4*>(&s_tile[srow0 + i][scol0]);
        float4 a = rowp[0], b = rowp[1], d = rowp[2];
        float v[12] = { a.x, a.y, a.z, a.w,
                        b.x, b.y, b.z, b.w,
                        d.x, d.y, d.z, d.w };
        #pragma unroll
        for (int r = 0; r < RY; ++r) {
            const int fi = i - r;            // filter row hitting output row r
            if (fi < 0 || fi > 4) continue;  // compile-time dead-code elim
            #pragma unroll
            for (int c = 0; c < RX; ++c) {
                #pragma unroll
                for (int fc = 0; fc < 5; ++fc) {
                    acc[r][c] = fminf(acc[r][c], v[c + fc + 2] + nf[fi * 5 + fc]);
                }
            }
        }
    }

    // ---- store 4x4 block, float4 per row ----
    float* __restrict__ o = out + (size_t)blockIdx.z * (size_t)(WIDTH * HEIGHT);
    const int oy = y0 + ty * RY;
    const int ox = x0 + tx * RX;
    #pragma unroll
    for (int r = 0; r < RY; ++r) {
        float4 w = make_float4(acc[r][0], acc[r][1], acc[r][2], acc[r][3]);
        *reinterpret_cast<float4*>(o + (size_t)(oy + r) * WIDTH + ox) = w;
    }
}

extern "C" void kernel_launch(void* const* d_in, const int* in_sizes, int n_in,
                              void* d_out, int out_size)
{
    const float* img  = (const float*)d_in[0];
    const float* filt = (const float*)d_in[1];
    float* out        = (float*)d_out;

    const int planes = in_sizes[0] / (WIDTH * HEIGHT);   // 32*3 = 96

    dim3 block(BDX, BDY);
    dim3 grid(WIDTH / TILE_X, HEIGHT / TILE_Y, planes);
    erosion5x5_kernel<<<grid, block>>>(img, filt, out);
}

// round 8
// speedup vs baseline: 1.0070x; 1.0070x over previous
#include <cuda_runtime.h>
#include <cstdint>

// Grayscale erosion, 5x5 non-flat SE, 'same' padding with +inf.
// out[p,y,x] = min_{i,j in 0..4} img[p, y+i-2, x+j-2] - filt[i,j]
//
// Compute-bound design: 50 fp32 ops/pixel is the floor (25 FADD + 25 FMNMX).
// Register-block 4x4 outputs per thread; stage input tile in smem with
// vectorized fill (interior fast path) and vectorized LDS.128 patch reads.

#define WIDTH   1024
#define HEIGHT  1024
#define TILE_X  128      // output cols per block
#define TILE_Y  32       // output rows per block
#define RX      4        // output cols per thread
#define RY      4        // output rows per thread
#define BDX     32       // TILE_X / RX
#define BDY     8        // TILE_Y / RY
// smem tile covers gmem cols [x0-4, x0+131] (2 wasted cols each side for
// 16B-aligned vector loads) and rows [y0-2, y0+33].
#define SW      136
#define SH      36
#define SW4     (SW/4)   // 34 float4 per row
#define FINF    __int_as_float(0x7f800000)

__global__ __launch_bounds__(BDX * BDY)
void erosion5x5_kernel(const float* __restrict__ img,
                       const float* __restrict__ filt,
                       float* __restrict__ out)
{
    __shared__ __align__(16) float s_tile[SH][SW];
    __shared__ float s_nf[25];

    const int tx  = threadIdx.x;           // 0..31
    const int ty  = threadIdx.y;           // 0..7
    const int tid = ty * BDX + tx;         // 0..255

    const int x0 = blockIdx.x * TILE_X;
    const int y0 = blockIdx.y * TILE_Y;
    const float* __restrict__ p =
        img + (size_t)blockIdx.z * (size_t)(WIDTH * HEIGHT);

    // negated filter -> smem (so inner loop is FADD, min identity preserved)
    if (tid < 25) s_nf[tid] = -filt[tid];

    // ---- stage input tile into smem ----
    const bool interior = (x0 >= 4) && (x0 + SW - 4 <= WIDTH) &&
                          (y0 >= 2) && (y0 + SH - 2 <= HEIGHT);
    if (interior) {
        // 34*36 = 1224 float4 transfers, fully aligned, no bounds checks
        const float4* __restrict__ g =
            reinterpret_cast<const float4*>(p + (size_t)(y0 - 2) * WIDTH + (x0 - 4));
        float4* __restrict__ s = reinterpret_cast<float4*>(&s_tile[0][0]);
        #pragma unroll
        for (int q = tid; q < SH * SW4; q += BDX * BDY) {
            int r  = q / SW4;
            int c4 = q - r * SW4;
            s[q] = g[(size_t)r * (WIDTH / 4) + c4];
        }
    } else {
        // scalar fill with +inf padding
        for (int idx = tid; idx < SH * SW; idx += BDX * BDY) {
            int r  = idx / SW;
            int c  = idx - r * SW;
            int gr = y0 - 2 + r;
            int gc = x0 - 4 + c;
            float v = FINF;
            if (gr >= 0 && gr < HEIGHT && gc >= 0 && gc < WIDTH)
                v = p[(size_t)gr * WIDTH + gc];
            s_tile[r][c] = v;
        }
    }
    __syncthreads();

    // negated filter into registers (LDS broadcast, conflict-free)
    float nf[25];
    #pragma unroll
    for (int i = 0; i < 25; ++i) nf[i] = s_nf[i];

    // ---- compute 4x4 outputs per thread ----
    float acc[RY][RX];
    #pragma unroll
    for (int r = 0; r < RY; ++r)
        #pragma unroll
        for (int c = 0; c < RX; ++c)
            acc[r][c] = FINF;

    const int srow0 = ty * RY;      // smem row of patch row 0 (= output row 0 - 2, rebased)
    const int scol0 = tx * RX;      // smem col of patch col 0 (= output col 0 - 2, rebased w/ +2 skew)

    #pragma unroll
    for (int i = 0; i < RY + 4; ++i) {
        // load 12 contiguous floats (3x LDS.128), patch uses v[2..9]
        const float4* rowp =
            reinterpret_cast<const float4*>(&s_tile[srow0 + i][scol0]);
        float4 a = rowp[0], b = rowp[1], d = rowp[2];
        float v[12] = { a.x, a.y, a.z, a.w,
                        b.x, b.y, b.z, b.w,
                        d.x, d.y, d.z, d.w };
        #pragma unroll
        for (int r = 0; r < RY; ++r) {
            const int fi = i - r;            // filter row hitting output row r
            if (fi < 0 || fi > 4) continue;  // compile-time dead-code elim
            #pragma unroll
            for (int c = 0; c < RX; ++c) {
                #pragma unroll
                for (int fc = 0; fc < 5; ++fc) {
                    acc[r][c] = fminf(acc[r][c], v[c + fc + 2] + nf[fi * 5 + fc]);
                }
            }
        }
    }

    // ---- store 4x4 block, float4 per row ----
    float* __restrict__ o = out + (size_t)blockIdx.z * (size_t)(WIDTH * HEIGHT);
    const int oy = y0 + ty * RY;
    const int ox = x0 + tx * RX;
    #pragma unroll
    for (int r = 0; r < RY; ++r) {
        float4 w = make_float4(acc[r][0], acc[r][1], acc[r][2], acc[r][3]);
        *reinterpret_cast<float4*>(o + (size_t)(oy + r) * WIDTH + ox) = w;
    }
}

extern "C" void kernel_launch(void* const* d_in, const int* in_sizes, int n_in,
                              void* d_out, int out_size)
{
    const float* img  = (const float*)d_in[0];
    const float* filt = (const float*)d_in[1];
    float* out        = (float*)d_out;

    const int planes = in_sizes[0] / (WIDTH * HEIGHT);   // 32*3 = 96

    dim3 block(BDX, BDY);
    dim3 grid(WIDTH / TILE_X, HEIGHT / TILE_Y, planes);
    erosion5x5_kernel<<<grid, block>>>(img, filt, out);
}

// round 11
// speedup vs baseline: 1.0110x; 1.0040x over previous
#include <cuda_runtime.h>
#include <cstdint>

// Grayscale erosion, 5x5 non-flat SE, 'same' padding with +inf.
// out[p,y,x] = min_{i,j in 0..4} img[p, y+i-2, x+j-2] - filt[i,j]
//
// fp32 scalar floor: 25 FADD + 24 FMNMX per pixel (issue-cap == alu-pipe cap
// ~= 140us). This version removes the fill-latency stalls of the one-shot
// tile kernel: each block sweeps 4 vertical tiles with double-buffered smem
// and register-staged prefetch (LDG before compute, STS after), 1 sync/iter.

#define WIDTH   1024
#define HEIGHT  1024
#define TILE_X  128
#define TILE_Y  32
#define ITERS   4
#define YSPAN   (TILE_Y * ITERS)     // 128
#define XT      (WIDTH / TILE_X)     // 8
#define YT      (HEIGHT / YSPAN)     // 8
#define RX      4
#define RY      4
#define BDX     32
#define BDY     8
#define NTHR    (BDX * BDY)          // 256
// smem tile: gmem cols [x0-4, x0+131] (16B-aligned vec loads), rows [y0-2, y0+33]
#define SW      136
#define SH      36
#define SW4     (SW / 4)             // 34 float4 per row
#define NV4     (SH * SW4)           // 1224 float4 per tile
#define FINF    __int_as_float(0x7f800000)

__global__ __launch_bounds__(NTHR)
void erosion5x5_kernel(const float* __restrict__ img,
                       const float* __restrict__ filt,
                       float* __restrict__ out)
{
    __shared__ __align__(16) float s_tile[2][SH][SW];
    __shared__ float s_nf[25];

    const int tx  = threadIdx.x;            // 0..31
    const int ty  = threadIdx.y;            // 0..7
    const int tid = ty * BDX + tx;          // 0..255

    const int x0    = blockIdx.x * TILE_X;
    const int ybase = blockIdx.y * YSPAN;
    const size_t plane = (size_t)blockIdx.z * (size_t)(WIDTH * HEIGHT);
    const float* __restrict__ p = img + plane;
    float* __restrict__ o       = out + plane;

    const bool xInterior = (x0 >= 4) && (x0 + SW - 4 <= WIDTH);

    // negated filter (min identity preserved under +)
    if (tid < 25) s_nf[tid] = -filt[tid];

    // ---------------- fill helpers ----------------
    auto fill_fast = [&](int buf, int y0) {
        const float4* __restrict__ g =
            reinterpret_cast<const float4*>(p + (size_t)(y0 - 2) * WIDTH + (x0 - 4));
        float4* __restrict__ s = reinterpret_cast<float4*>(&s_tile[buf][0][0]);
        #pragma unroll
        for (int k = 0; k < 5; ++k) {
            int q = tid + k * NTHR;
            if (q < NV4) {
                int r  = q / SW4;
                int c4 = q - r * SW4;
                s[q] = g[(size_t)r * (WIDTH / 4) + c4];
            }
        }
    };
    auto fill_guarded = [&](int buf, int y0) {
        for (int idx = tid; idx < SH * SW; idx += NTHR) {
            int r  = idx / SW;
            int c  = idx - r * SW;
            int gr = y0 - 2 + r;
            int gc = x0 - 4 + c;
            float v = FINF;
            if (gr >= 0 && gr < HEIGHT && gc >= 0 && gc < WIDTH)
                v = p[(size_t)gr * WIDTH + gc];
            s_tile[buf][r][c] = v;
        }
    };
    auto fast_ok = [&](int y0) {
        return xInterior && (y0 >= 2) && (y0 + SH - 2 <= HEIGHT);
    };

    // initial fill of buffer 0
    if (fast_ok(ybase)) fill_fast(0, ybase);
    else                fill_guarded(0, ybase);
    __syncthreads();

    // filter into registers (LDS broadcast)
    float nf[25];
    #pragma unroll
    for (int i = 0; i < 25; ++i) nf[i] = s_nf[i];

    const int srow0 = ty * RY;
    const int scol0 = tx * RX;

    for (int t = 0; t < ITERS; ++t) {
        const int  cur   = t & 1;
        const int  y0    = ybase + t * TILE_Y;
        const bool last  = (t == ITERS - 1);
        const int  y0n   = y0 + TILE_Y;
        const bool fastN = !last && fast_ok(y0n);

        // ---- register-staged prefetch of next tile (hidden under compute) ----
        float4 pre[5];
        if (fastN) {
            const float4* __restrict__ g =
                reinterpret_cast<const float4*>(p + (size_t)(y0n - 2) * WIDTH + (x0 - 4));
            #pragma unroll
            for (int k = 0; k < 5; ++k) {
                int q = tid + k * NTHR;
                if (q < NV4) {
                    int r  = q / SW4;
                    int c4 = q - r * SW4;
                    pre[k] = g[(size_t)r * (WIDTH / 4) + c4];
                }
            }
        }

        // ---- compute 4x4 outputs per thread ----
        float acc[RY][RX];
        #pragma unroll
        for (int i = 0; i < RY + 4; ++i) {
            const float4* rowp =
                reinterpret_cast<const float4*>(&s_tile[cur][srow0 + i][scol0]);
            float4 a = rowp[0], b = rowp[1], d = rowp[2];
            float v[12] = { a.x, a.y, a.z, a.w,
                            b.x, b.y, b.z, b.w,
                            d.x, d.y, d.z, d.w };
            #pragma unroll
            for (int r = 0; r < RY; ++r) {
                const int fi = i - r;            // filter row hitting output row r
                if (fi < 0 || fi > 4) continue;  // compile-time DCE
                #pragma unroll
                for (int c = 0; c < RX; ++c) {
                    #pragma unroll
                    for (int fc = 0; fc < 5; ++fc) {
                        float cand = v[c + fc + 2] + nf[fi * 5 + fc];
                        if (fi == 0 && fc == 0) acc[r][c] = cand;  // first touch
                        else                    acc[r][c] = fminf(acc[r][c], cand);
                    }
                }
            }
        }

        // ---- store 4x4 block ----
        const int oy = y0 + ty * RY;
        const int ox = x0 + tx * RX;
        #pragma unroll
        for (int r = 0; r < RY; ++r) {
            float4 w = make_float4(acc[r][0], acc[r][1], acc[r][2], acc[r][3]);
            *reinterpret_cast<float4*>(o + (size_t)(oy + r) * WIDTH + ox) = w;
        }

        // ---- commit next tile to the other buffer ----
        if (!last) {
            if (fastN) {
                float4* __restrict__ s =
                    reinterpret_cast<float4*>(&s_tile[cur ^ 1][0][0]);
                #pragma unroll
                for (int k = 0; k < 5; ++k) {
                    int q = tid + k * NTHR;
                    if (q < NV4) s[q] = pre[k];
                }
            } else {
                fill_guarded(cur ^ 1, y0n);
            }
        }
        __syncthreads();
    }
}

extern "C" void kernel_launch(void* const* d_in, const int* in_sizes, int n_in,
                              void* d_out, int out_size)
{
    const float* img  = (const float*)d_in[0];
    const float* filt = (const float*)d_in[1];
    float* out        = (float*)d_out;

    const int planes = in_sizes[0] / (WIDTH * HEIGHT);   // 32*3 = 96

    dim3 block(BDX, BDY);
    dim3 grid(XT, YT, planes);
    erosion5x5_kernel<<<grid, block>>>(img, filt, out);
}